// round 16
// baseline (speedup 1.0000x reference)
#include <cuda_runtime.h>
#include <cuda_fp16.h>
#include <cstdint>
#include <math.h>

#define BB 4
#define SSEQ 2048
#define DIMX 512
#define HEADS 8
#define DHEAD 64
#define INNER 512
#define NROWS (BB * SSEQ)   // 8192
#define NX  (NROWS * DIMX)  // 4194304

// ---------------- device scratch -------------------------------------------
__device__ __half g_x[NX];
__device__ __half g_wq[3 * INNER * DIMX];   // W_qkv^T [1536][512]
__device__ __half g_wo[DIMX * INNER];       // W_out^T [512][512]
__device__ __half g_q[NROWS * INNER];       // [bh][s][64], pre-scaled
__device__ __half g_k[NROWS * INNER];
__device__ __half g_v[NROWS * INNER];
__device__ __half g_a[NROWS * INNER];       // [b*s][512]

// ---------------- helpers ---------------------------------------------------
__device__ __forceinline__ uint32_t smem_u32(const void* p) {
    uint32_t a;
    asm("{ .reg .u64 t; cvta.to.shared.u64 t, %1; cvt.u32.u64 %0, t; }" : "=r"(a) : "l"(p));
    return a;
}
__device__ __forceinline__ void ldsm4(uint32_t& r0, uint32_t& r1, uint32_t& r2,
                                      uint32_t& r3, uint32_t addr) {
    asm volatile("ldmatrix.sync.aligned.m8n8.x4.shared.b16 {%0,%1,%2,%3}, [%4];"
                 : "=r"(r0), "=r"(r1), "=r"(r2), "=r"(r3) : "r"(addr));
}
__device__ __forceinline__ void ldsm4t(uint32_t& r0, uint32_t& r1, uint32_t& r2,
                                       uint32_t& r3, uint32_t addr) {
    asm volatile("ldmatrix.sync.aligned.m8n8.x4.trans.shared.b16 {%0,%1,%2,%3}, [%4];"
                 : "=r"(r0), "=r"(r1), "=r"(r2), "=r"(r3) : "r"(addr));
}
__device__ __forceinline__ void mma_f16(float* c, const uint32_t a[4],
                                        uint32_t b0, uint32_t b1) {
    asm volatile(
        "mma.sync.aligned.m16n8k16.row.col.f32.f16.f16.f32 "
        "{%0,%1,%2,%3}, {%4,%5,%6,%7}, {%8,%9}, {%0,%1,%2,%3};"
        : "+f"(c[0]), "+f"(c[1]), "+f"(c[2]), "+f"(c[3])
        : "r"(a[0]), "r"(a[1]), "r"(a[2]), "r"(a[3]), "r"(b0), "r"(b1));
}
__device__ __forceinline__ void cp16(uint32_t dst, const void* src) {
    asm volatile("cp.async.cg.shared.global [%0], [%1], 16;" :: "r"(dst), "l"(src));
}
#define CP_COMMIT() asm volatile("cp.async.commit_group;" ::: "memory")
#define CP_WAIT1()  asm volatile("cp.async.wait_group 1;" ::: "memory")
#define CP_WAIT2()  asm volatile("cp.async.wait_group 2;" ::: "memory")

__device__ __forceinline__ uint32_t pkh(float a, float b) {   // a in low half
    __half2 x = __floats2half2_rn(a, b);
    return *reinterpret_cast<uint32_t*>(&x);
}
// 16B-chunk swizzle within 128B rows (conflict-free ldmatrix)
__device__ __forceinline__ uint32_t swz(int r, int c) {
    return (uint32_t)r * 128u + (uint32_t)((c ^ (r & 7)) & 7) * 16u;
}

// ---------------- fused convert kernel (unchanged) ---------------------------
__global__ void __launch_bounds__(256, 8)
k_convert(const float* __restrict__ x, const float* __restrict__ Wq,
          const float* __restrict__ Wo,
          __half* __restrict__ xo, __half* __restrict__ wqo,
          __half* __restrict__ woo) {
    __shared__ float t[32][33];
    const int bid = blockIdx.x, tid = threadIdx.x;
    if (bid < 4096) {
        int i = bid * 1024 + tid * 4;
        float4 f = *reinterpret_cast<const float4*>(x + i);
        uint32_t p0 = pkh(f.x, f.y), p1 = pkh(f.z, f.w);
        *reinterpret_cast<uint2*>(xo + i) = make_uint2(p0, p1);
        return;
    }
    const int tx = tid & 31, ty = tid >> 5;   // 32 x 8
    const float* in;
    __half* o;
    int K, N, bn, bk;
    if (bid < 4096 + 768) {
        int j = bid - 4096;
        in = Wq; o = wqo; K = 512; N = 1536;
        bn = (j % 48) * 32; bk = (j / 48) * 32;
    } else {
        int j = bid - 4096 - 768;
        in = Wo; o = woo; K = 512; N = 512;
        bn = (j % 16) * 32; bk = (j / 16) * 32;
    }
#pragma unroll
    for (int j = 0; j < 32; j += 8)
        t[ty + j][tx] = in[(size_t)(bk + ty + j) * N + bn + tx];
    __syncthreads();
#pragma unroll
    for (int j = 0; j < 32; j += 8)
        o[(size_t)(bn + ty + j) * K + bk + tx] = __float2half_rn(t[tx][ty + j]);
}

// ---------------- fp16 GEMM (unchanged from R15) -----------------------------
template <int MODE>
__global__ void __launch_bounds__(256, 2)
gemm_mma(const __half* __restrict__ Ah, const __half* __restrict__ Bh, int Kd,
         __half* __restrict__ q, __half* __restrict__ k, __half* __restrict__ v,
         const float* __restrict__ log_temp,
         const float* __restrict__ bias, float* __restrict__ outp) {
    extern __shared__ char smc[];
    const uint32_t sb = smem_u32(smc);
    const int tid = threadIdx.x, w = tid >> 5, lane = tid & 31;
    const int m0 = blockIdx.y * 128, n0 = blockIdx.x * 128;
    const int wm = w & 3, wn = w >> 2;
    const uint32_t STG = 32768;

    float acc[2][8][4] = {};

    auto issue = [&](int kc, int stg) {
        uint32_t base = sb + (uint32_t)stg * STG;
#pragma unroll
        for (int i = tid; i < 1024; i += 256) {
            int r = i >> 3, c = i & 7;
            uint32_t off = swz(r, c);
            cp16(base + off,         Ah + (size_t)(m0 + r) * Kd + kc + c * 8);
            cp16(base + 16384 + off, Bh + (size_t)(n0 + r) * Kd + kc + c * 8);
        }
    };

    const int nch = Kd / 64;
    issue(0, 0); CP_COMMIT();
    issue(64, 1); CP_COMMIT();

    int stg = 0, nstg = 2;
    for (int kc = 0; kc < nch; kc++) {
        if (kc + 2 < nch) issue((kc + 2) * 64, nstg);
        CP_COMMIT();
        CP_WAIT2();
        __syncthreads();

        const uint32_t As = sb + (uint32_t)stg * STG;
        const uint32_t Bs = As + 16384;
#pragma unroll
        for (int ks = 0; ks < 4; ks++) {
            uint32_t ah[2][4];
#pragma unroll
            for (int mt = 0; mt < 2; mt++) {
                int rr = 32 * wm + 16 * mt + (lane & 7) + ((lane >> 3) & 1) * 8;
                int cc = 2 * ks + (lane >> 4);
                ldsm4(ah[mt][0], ah[mt][1], ah[mt][2], ah[mt][3], As + swz(rr, cc));
            }
#pragma unroll
            for (int nb = 0; nb < 4; nb++) {
                int rr = 64 * wn + 16 * nb + (lane & 7) + ((lane >> 4) ? 8 : 0);
                int cc = 2 * ks + ((lane >> 3) & 1);
                uint32_t b0, b1, b2, b3;
                ldsm4(b0, b1, b2, b3, Bs + swz(rr, cc));
#pragma unroll
                for (int mt = 0; mt < 2; mt++) {
                    mma_f16(acc[mt][2 * nb],     ah[mt], b0, b1);
                    mma_f16(acc[mt][2 * nb + 1], ah[mt], b2, b3);
                }
            }
        }
        __syncthreads();
        stg = (stg + 1 == 3) ? 0 : stg + 1;
        nstg = (nstg + 1 == 3) ? 0 : nstg + 1;
    }

    const float qscale = (MODE == 0) ? __expf(*log_temp) * 1.4426950408889634f : 1.f;
#pragma unroll
    for (int mt = 0; mt < 2; mt++) {
#pragma unroll
        for (int i = 0; i < 2; i++) {
            const int gm = m0 + 32 * wm + 16 * mt + (lane >> 2) + i * 8;
#pragma unroll
            for (int nt = 0; nt < 8; nt++) {
                const int gn = n0 + 64 * wn + 8 * nt + 2 * (lane & 3);
                float v0 = acc[mt][nt][2 * i], v1 = acc[mt][nt][2 * i + 1];
                if (MODE == 0) {
                    const int seg = gn >> 9, nn = gn & 511;
                    const int h = nn >> 6, d = nn & 63;
                    const int bI = gm >> 11, s = gm & 2047;
                    size_t idx = ((size_t)((bI * 8 + h) * 2048 + s)) * 64 + d;
                    if (seg == 0) { v0 *= qscale; v1 *= qscale; }
                    __half* dst = (seg == 0) ? q : (seg == 1) ? k : v;
                    *reinterpret_cast<uint32_t*>(dst + idx) = pkh(v0, v1);
                } else {
                    float2 bb = *reinterpret_cast<const float2*>(bias + gn);
                    float2 o = make_float2(v0 + bb.x, v1 + bb.y);
                    *reinterpret_cast<float2*>(outp + (size_t)gm * 512 + gn) = o;
                }
            }
        }
    }
}

// ---------------- attention v4: q-tile 128, 128 threads, 2 CTAs/SM -----------
// 4 warps x m32; per-warp work per tile identical to v2/v3 (K/V fragment reuse
// across both m16 tiles). Half-size CTAs kill the 2-wave quantization loss.
__global__ void __launch_bounds__(128, 2)
attn_mma(const __half* __restrict__ qg, const __half* __restrict__ kg,
         const __half* __restrict__ vg, __half* __restrict__ aout) {
    extern __shared__ char smc[];
    const uint32_t sb = smem_u32(smc);
    const int tid = threadIdx.x, w = tid >> 5, lane = tid & 31;
    const int q0 = blockIdx.x * 128;
    const int bh = blockIdx.y, b = bh >> 3, h = bh & 7;
    const uint32_t KO = 0, VO = 16384, STG = 32768, QO = 65536;  // 2 stages + Q

    const size_t bho = (size_t)bh * 2048 * 64;

    // Q tile (128 x 64) -> smem
#pragma unroll
    for (int i = tid; i < 1024; i += 128) {
        int r = i >> 3, c = i & 7;
        *reinterpret_cast<uint4*>(smc + QO + swz(r, c)) =
            *reinterpret_cast<const uint4*>(qg + bho + (size_t)(q0 + r) * 64 + c * 8);
    }

    auto issue = [&](int t, int stg) {
        const size_t o = bho + (size_t)t * 128 * 64;
        uint32_t base = sb + (uint32_t)stg * STG;
#pragma unroll
        for (int i = tid; i < 1024; i += 128) {
            int r = i >> 3, c = i & 7;
            uint32_t off = swz(r, c);
            size_t g = o + (size_t)r * 64 + c * 8;
            cp16(base + KO + off, kg + g);
            cp16(base + VO + off, vg + g);
        }
    };
    issue(0, 0); CP_COMMIT();
    __syncthreads();   // Q visible

    // Q fragments for both m16 tiles (persist)
    uint32_t aq[2][4][4];
#pragma unroll
    for (int mt = 0; mt < 2; mt++) {
        int rr = 32 * w + 16 * mt + (lane & 7) + ((lane >> 3) & 1) * 8;
#pragma unroll
        for (int ks = 0; ks < 4; ks++) {
            int cc = 2 * ks + (lane >> 4);
            ldsm4(aq[mt][ks][0], aq[mt][ks][1], aq[mt][ks][2], aq[mt][ks][3],
                  sb + QO + swz(rr, cc));
        }
    }

    float O[2][8][4] = {};
    float l[2][2] = {};
    const int rbase = q0 + 32 * w + (lane >> 2);

    for (int t = 0; t < 16; t++) {
        if (t + 1 < 16) issue(t + 1, (t + 1) & 1);
        CP_COMMIT();
        CP_WAIT1();
        __syncthreads();

        const uint32_t stgb = sb + (uint32_t)(t & 1) * STG;
        const uint32_t Ks = stgb + KO, Vs = stgb + VO;

#pragma unroll
        for (int half = 0; half < 2; half++) {
            float S[2][8][4] = {};
#pragma unroll
            for (int ks = 0; ks < 4; ks++) {
#pragma unroll
                for (int ntp = 0; ntp < 4; ntp++) {
                    uint32_t b0, b1, b2, b3;
                    int rr = 16 * (4 * half + ntp) + (lane & 7) + ((lane >> 4) ? 8 : 0);
                    int cc = 2 * ks + ((lane >> 3) & 1);
                    ldsm4(b0, b1, b2, b3, Ks + swz(rr, cc));
#pragma unroll
                    for (int mt = 0; mt < 2; mt++) {
                        mma_f16(S[mt][2 * ntp],     aq[mt][ks], b0, b1);
                        mma_f16(S[mt][2 * ntp + 1], aq[mt][ks], b2, b3);
                    }
                }
            }

            uint32_t ep[2][8][2];
#pragma unroll
            for (int mt = 0; mt < 2; mt++) {
                const int qi0 = rbase + 16 * mt, qi1 = qi0 + 8;
#pragma unroll
                for (int s = 0; s < 8; s++) {
                    int jc = t * 128 + 64 * half + 8 * s + 2 * (lane & 3);
                    float e0 = (jc     == qi0) ? 0.f : exp2f(S[mt][s][0]);
                    float e1 = (jc + 1 == qi0) ? 0.f : exp2f(S[mt][s][1]);
                    float e2 = (jc     == qi1) ? 0.f : exp2f(S[mt][s][2]);
                    float e3 = (jc + 1 == qi1) ? 0.f : exp2f(S[mt][s][3]);
                    l[mt][0] += e0 + e1;
                    l[mt][1] += e2 + e3;
                    ep[mt][s][0] = pkh(e0, e1);
                    ep[mt][s][1] = pkh(e2, e3);
                }
            }

#pragma unroll
            for (int ks2 = 0; ks2 < 4; ks2++) {
#pragma unroll
                for (int ntp = 0; ntp < 4; ntp++) {
                    uint32_t b0, b1, b2, b3;
                    int rr = 16 * (4 * half + ks2) + (lane & 7) + ((lane >> 3) & 1) * 8;
                    int cc = 2 * ntp + (lane >> 4);
                    ldsm4t(b0, b1, b2, b3, Vs + swz(rr, cc));
#pragma unroll
                    for (int mt = 0; mt < 2; mt++) {
                        uint32_t ap[4] = { ep[mt][2 * ks2][0], ep[mt][2 * ks2][1],
                                           ep[mt][2 * ks2 + 1][0], ep[mt][2 * ks2 + 1][1] };
                        mma_f16(O[mt][2 * ntp],     ap, b0, b1);
                        mma_f16(O[mt][2 * ntp + 1], ap, b2, b3);
                    }
                }
            }
        }
        __syncthreads();   // stage t free before overwrite (2-stage ring)
    }

#pragma unroll
    for (int mt = 0; mt < 2; mt++) {
#pragma unroll
        for (int i = 0; i < 2; i++) {
            float li = l[mt][i];
            li += __shfl_xor_sync(0xffffffffu, li, 1);
            li += __shfl_xor_sync(0xffffffffu, li, 2);
            const float inv = 1.f / li;
            const size_t gm = (size_t)(b * 2048 + rbase + 16 * mt + 8 * i);
#pragma unroll
            for (int nt = 0; nt < 8; nt++) {
                const int d = 8 * nt + 2 * (lane & 3);
                size_t idx = gm * INNER + h * DHEAD + d;
                *reinterpret_cast<uint32_t*>(aout + idx) =
                    pkh(O[mt][nt][2 * i] * inv, O[mt][nt][2 * i + 1] * inv);
            }
        }
    }
}

// ---------------- launch -----------------------------------------------------
extern "C" void kernel_launch(void* const* d_in, const int* in_sizes, int n_in,
                              void* d_out, int out_size) {
    const float* x        = (const float*)d_in[0];
    const float* W_qkv    = (const float*)d_in[1];
    const float* log_temp = (const float*)d_in[2];
    const float* W_out    = (const float*)d_in[3];
    const float* b_out    = (const float*)d_in[4];
    float* out = (float*)d_out;

    __half *xh, *wq, *wo, *q, *k, *v, *a;
    cudaGetSymbolAddress((void**)&xh, g_x);
    cudaGetSymbolAddress((void**)&wq, g_wq);
    cudaGetSymbolAddress((void**)&wo, g_wo);
    cudaGetSymbolAddress((void**)&q, g_q);
    cudaGetSymbolAddress((void**)&k, g_k);
    cudaGetSymbolAddress((void**)&v, g_v);
    cudaGetSymbolAddress((void**)&a, g_a);

    const int GSM = 98304;    // 3 stages x 32KB
    const int ASM = 81920;    // 2 KV stages x 32KB + Q 16KB
    cudaFuncSetAttribute(gemm_mma<0>, cudaFuncAttributeMaxDynamicSharedMemorySize, GSM);
    cudaFuncSetAttribute(gemm_mma<1>, cudaFuncAttributeMaxDynamicSharedMemorySize, GSM);
    cudaFuncSetAttribute(attn_mma,    cudaFuncAttributeMaxDynamicSharedMemorySize, ASM);

    k_convert<<<5120, 256>>>(x, W_qkv, W_out, xh, wq, wo);

    // 1) QKV projection (q pre-scaled by exp(log_temp)*log2e)
    gemm_mma<0><<<dim3(12, 64), 256, GSM>>>(xh, wq, DIMX, q, k, v,
                                            log_temp, nullptr, nullptr);
    // 2) attention (q-tile 128, 128 threads, 2 CTAs/SM — no wave quantization)
    attn_mma<<<dim3(SSEQ / 128, BB * HEADS), 128, ASM>>>(q, k, v, a);
    // 3) output projection + bias -> fp32
    gemm_mma<1><<<dim3(4, 64), 256, GSM>>>(a, wo, INNER, nullptr, nullptr, nullptr,
                                           nullptr, b_out, out);
}

// round 17
// speedup vs baseline: 1.0230x; 1.0230x over previous
#include <cuda_runtime.h>
#include <cuda_fp16.h>
#include <cstdint>
#include <math.h>

#define BB 4
#define SSEQ 2048
#define DIMX 512
#define HEADS 8
#define DHEAD 64
#define INNER 512
#define NROWS (BB * SSEQ)   // 8192
#define NX  (NROWS * DIMX)  // 4194304

// ---------------- device scratch -------------------------------------------
__device__ __half g_x[NX];
__device__ __half g_wq[3 * INNER * DIMX];   // W_qkv^T [1536][512]
__device__ __half g_wo[DIMX * INNER];       // W_out^T [512][512]
__device__ __half g_q[NROWS * INNER];       // [bh][s][64], pre-scaled
__device__ __half g_k[NROWS * INNER];
__device__ __half g_v[NROWS * INNER];
__device__ __half g_a[NROWS * INNER];       // [b*s][512]

// ---------------- helpers ---------------------------------------------------
__device__ __forceinline__ uint32_t smem_u32(const void* p) {
    uint32_t a;
    asm("{ .reg .u64 t; cvta.to.shared.u64 t, %1; cvt.u32.u64 %0, t; }" : "=r"(a) : "l"(p));
    return a;
}
__device__ __forceinline__ void ldsm4(uint32_t& r0, uint32_t& r1, uint32_t& r2,
                                      uint32_t& r3, uint32_t addr) {
    asm volatile("ldmatrix.sync.aligned.m8n8.x4.shared.b16 {%0,%1,%2,%3}, [%4];"
                 : "=r"(r0), "=r"(r1), "=r"(r2), "=r"(r3) : "r"(addr));
}
__device__ __forceinline__ void ldsm4t(uint32_t& r0, uint32_t& r1, uint32_t& r2,
                                       uint32_t& r3, uint32_t addr) {
    asm volatile("ldmatrix.sync.aligned.m8n8.x4.trans.shared.b16 {%0,%1,%2,%3}, [%4];"
                 : "=r"(r0), "=r"(r1), "=r"(r2), "=r"(r3) : "r"(addr));
}
__device__ __forceinline__ void mma_f16(float* c, const uint32_t a[4],
                                        uint32_t b0, uint32_t b1) {
    asm volatile(
        "mma.sync.aligned.m16n8k16.row.col.f32.f16.f16.f32 "
        "{%0,%1,%2,%3}, {%4,%5,%6,%7}, {%8,%9}, {%0,%1,%2,%3};"
        : "+f"(c[0]), "+f"(c[1]), "+f"(c[2]), "+f"(c[3])
        : "r"(a[0]), "r"(a[1]), "r"(a[2]), "r"(a[3]), "r"(b0), "r"(b1));
}
__device__ __forceinline__ void cp16(uint32_t dst, const void* src) {
    asm volatile("cp.async.cg.shared.global [%0], [%1], 16;" :: "r"(dst), "l"(src));
}
#define CP_COMMIT() asm volatile("cp.async.commit_group;" ::: "memory")
#define CP_WAIT1()  asm volatile("cp.async.wait_group 1;" ::: "memory")
#define CP_WAIT2()  asm volatile("cp.async.wait_group 2;" ::: "memory")

__device__ __forceinline__ uint32_t pkh(float a, float b) {   // a in low half
    __half2 x = __floats2half2_rn(a, b);
    return *reinterpret_cast<uint32_t*>(&x);
}
// 16B-chunk swizzle within 128B rows (conflict-free ldmatrix)
__device__ __forceinline__ uint32_t swz(int r, int c) {
    return (uint32_t)r * 128u + (uint32_t)((c ^ (r & 7)) & 7) * 16u;
}

// ---------------- fused convert kernel ---------------------------------------
__global__ void __launch_bounds__(256, 8)
k_convert(const float* __restrict__ x, const float* __restrict__ Wq,
          const float* __restrict__ Wo,
          __half* __restrict__ xo, __half* __restrict__ wqo,
          __half* __restrict__ woo) {
    __shared__ float t[32][33];
    const int bid = blockIdx.x, tid = threadIdx.x;
    if (bid < 4096) {
        int i = bid * 1024 + tid * 4;
        float4 f = *reinterpret_cast<const float4*>(x + i);
        uint32_t p0 = pkh(f.x, f.y), p1 = pkh(f.z, f.w);
        *reinterpret_cast<uint2*>(xo + i) = make_uint2(p0, p1);
        return;
    }
    const int tx = tid & 31, ty = tid >> 5;   // 32 x 8
    const float* in;
    __half* o;
    int K, N, bn, bk;
    if (bid < 4096 + 768) {
        int j = bid - 4096;
        in = Wq; o = wqo; K = 512; N = 1536;
        bn = (j % 48) * 32; bk = (j / 48) * 32;
    } else {
        int j = bid - 4096 - 768;
        in = Wo; o = woo; K = 512; N = 512;
        bn = (j % 16) * 32; bk = (j / 16) * 32;
    }
#pragma unroll
    for (int j = 0; j < 32; j += 8)
        t[ty + j][tx] = in[(size_t)(bk + ty + j) * N + bn + tx];
    __syncthreads();
#pragma unroll
    for (int j = 0; j < 32; j += 8)
        o[(size_t)(bn + ty + j) * K + bk + tx] = __float2half_rn(t[tx][ty + j]);
}

// ---------------- fp16 GEMM, 256 threads, 2 CTAs/SM, 3-stage ring ------------
template <int MODE>
__global__ void __launch_bounds__(256, 2)
gemm_mma(const __half* __restrict__ Ah, const __half* __restrict__ Bh, int Kd,
         __half* __restrict__ q, __half* __restrict__ k, __half* __restrict__ v,
         const float* __restrict__ log_temp,
         const float* __restrict__ bias, float* __restrict__ outp) {
    extern __shared__ char smc[];
    const uint32_t sb = smem_u32(smc);
    const int tid = threadIdx.x, w = tid >> 5, lane = tid & 31;
    const int m0 = blockIdx.y * 128, n0 = blockIdx.x * 128;
    const int wm = w & 3, wn = w >> 2;
    const uint32_t STG = 32768;

    float acc[2][8][4] = {};

    auto issue = [&](int kc, int stg) {
        uint32_t base = sb + (uint32_t)stg * STG;
#pragma unroll
        for (int i = tid; i < 1024; i += 256) {
            int r = i >> 3, c = i & 7;
            uint32_t off = swz(r, c);
            cp16(base + off,         Ah + (size_t)(m0 + r) * Kd + kc + c * 8);
            cp16(base + 16384 + off, Bh + (size_t)(n0 + r) * Kd + kc + c * 8);
        }
    };

    const int nch = Kd / 64;
    issue(0, 0); CP_COMMIT();
    issue(64, 1); CP_COMMIT();

    int stg = 0, nstg = 2;
    for (int kc = 0; kc < nch; kc++) {
        if (kc + 2 < nch) issue((kc + 2) * 64, nstg);
        CP_COMMIT();
        CP_WAIT2();
        __syncthreads();

        const uint32_t As = sb + (uint32_t)stg * STG;
        const uint32_t Bs = As + 16384;
#pragma unroll
        for (int ks = 0; ks < 4; ks++) {
            uint32_t ah[2][4];
#pragma unroll
            for (int mt = 0; mt < 2; mt++) {
                int rr = 32 * wm + 16 * mt + (lane & 7) + ((lane >> 3) & 1) * 8;
                int cc = 2 * ks + (lane >> 4);
                ldsm4(ah[mt][0], ah[mt][1], ah[mt][2], ah[mt][3], As + swz(rr, cc));
            }
#pragma unroll
            for (int nb = 0; nb < 4; nb++) {
                int rr = 64 * wn + 16 * nb + (lane & 7) + ((lane >> 4) ? 8 : 0);
                int cc = 2 * ks + ((lane >> 3) & 1);
                uint32_t b0, b1, b2, b3;
                ldsm4(b0, b1, b2, b3, Bs + swz(rr, cc));
#pragma unroll
                for (int mt = 0; mt < 2; mt++) {
                    mma_f16(acc[mt][2 * nb],     ah[mt], b0, b1);
                    mma_f16(acc[mt][2 * nb + 1], ah[mt], b2, b3);
                }
            }
        }
        __syncthreads();
        stg = (stg + 1 == 3) ? 0 : stg + 1;
        nstg = (nstg + 1 == 3) ? 0 : nstg + 1;
    }

    const float qscale = (MODE == 0) ? __expf(*log_temp) * 1.4426950408889634f : 1.f;
#pragma unroll
    for (int mt = 0; mt < 2; mt++) {
#pragma unroll
        for (int i = 0; i < 2; i++) {
            const int gm = m0 + 32 * wm + 16 * mt + (lane >> 2) + i * 8;
#pragma unroll
            for (int nt = 0; nt < 8; nt++) {
                const int gn = n0 + 64 * wn + 8 * nt + 2 * (lane & 3);
                float v0 = acc[mt][nt][2 * i], v1 = acc[mt][nt][2 * i + 1];
                if (MODE == 0) {
                    const int seg = gn >> 9, nn = gn & 511;
                    const int h = nn >> 6, d = nn & 63;
                    const int bI = gm >> 11, s = gm & 2047;
                    size_t idx = ((size_t)((bI * 8 + h) * 2048 + s)) * 64 + d;
                    if (seg == 0) { v0 *= qscale; v1 *= qscale; }
                    __half* dst = (seg == 0) ? q : (seg == 1) ? k : v;
                    *reinterpret_cast<uint32_t*>(dst + idx) = pkh(v0, v1);
                } else {
                    float2 bb = *reinterpret_cast<const float2*>(bias + gn);
                    float2 o = make_float2(v0 + bb.x, v1 + bb.y);
                    *reinterpret_cast<float2*>(outp + (size_t)gm * 512 + gn) = o;
                }
            }
        }
    }
}

// ---------------- attention: q-tile 256, 4-stage KV ring, 1 barrier/tile -----
__global__ void __launch_bounds__(256, 1)
attn_mma(const __half* __restrict__ qg, const __half* __restrict__ kg,
         const __half* __restrict__ vg, __half* __restrict__ aout) {
    extern __shared__ char smc[];
    const uint32_t sb = smem_u32(smc);
    const int tid = threadIdx.x, w = tid >> 5, lane = tid & 31;
    const int q0 = blockIdx.x * 256;
    const int bh = blockIdx.y, b = bh >> 3, h = bh & 7;
    const uint32_t KO = 0, VO = 16384, STG = 32768, QO = 131072;  // 4 stages then Q

    const size_t bho = (size_t)bh * 2048 * 64;

    // Q tile (256 x 64) -> smem
#pragma unroll
    for (int i = tid; i < 2048; i += 256) {
        int r = i >> 3, c = i & 7;
        *reinterpret_cast<uint4*>(smc + QO + swz(r, c)) =
            *reinterpret_cast<const uint4*>(qg + bho + (size_t)(q0 + r) * 64 + c * 8);
    }

    auto issue = [&](int t, int stg) {
        const size_t o = bho + (size_t)t * 128 * 64;
        uint32_t base = sb + (uint32_t)stg * STG;
#pragma unroll
        for (int i = tid; i < 1024; i += 256) {
            int r = i >> 3, c = i & 7;
            uint32_t off = swz(r, c);
            size_t g = o + (size_t)r * 64 + c * 8;
            cp16(base + KO + off, kg + g);
            cp16(base + VO + off, vg + g);
        }
    };
    issue(0, 0); CP_COMMIT();
    issue(1, 1); CP_COMMIT();
    __syncthreads();   // Q visible

    // Q fragments for both m16 tiles (persist)
    uint32_t aq[2][4][4];
#pragma unroll
    for (int mt = 0; mt < 2; mt++) {
        int rr = 32 * w + 16 * mt + (lane & 7) + ((lane >> 3) & 1) * 8;
#pragma unroll
        for (int ks = 0; ks < 4; ks++) {
            int cc = 2 * ks + (lane >> 4);
            ldsm4(aq[mt][ks][0], aq[mt][ks][1], aq[mt][ks][2], aq[mt][ks][3],
                  sb + QO + swz(rr, cc));
        }
    }

    float O[2][8][4] = {};
    float l[2][2] = {};
    const int rbase = q0 + 32 * w + (lane >> 2);

    for (int t = 0; t < 16; t++) {
        if (t + 2 < 16) issue(t + 2, (t + 2) & 3);
        CP_COMMIT();
        CP_WAIT2();
        __syncthreads();   // tile t loads complete (all threads)

        const uint32_t stgb = sb + (uint32_t)(t & 3) * STG;
        const uint32_t Ks = stgb + KO, Vs = stgb + VO;

#pragma unroll
        for (int half = 0; half < 2; half++) {
            float S[2][8][4] = {};
#pragma unroll
            for (int ks = 0; ks < 4; ks++) {
#pragma unroll
                for (int ntp = 0; ntp < 4; ntp++) {
                    uint32_t b0, b1, b2, b3;
                    int rr = 16 * (4 * half + ntp) + (lane & 7) + ((lane >> 4) ? 8 : 0);
                    int cc = 2 * ks + ((lane >> 3) & 1);
                    ldsm4(b0, b1, b2, b3, Ks + swz(rr, cc));
#pragma unroll
                    for (int mt = 0; mt < 2; mt++) {
                        mma_f16(S[mt][2 * ntp],     aq[mt][ks], b0, b1);
                        mma_f16(S[mt][2 * ntp + 1], aq[mt][ks], b2, b3);
                    }
                }
            }

            uint32_t ep[2][8][2];
#pragma unroll
            for (int mt = 0; mt < 2; mt++) {
                const int qi0 = rbase + 16 * mt, qi1 = qi0 + 8;
#pragma unroll
                for (int s = 0; s < 8; s++) {
                    int jc = t * 128 + 64 * half + 8 * s + 2 * (lane & 3);
                    float e0 = (jc     == qi0) ? 0.f : exp2f(S[mt][s][0]);
                    float e1 = (jc + 1 == qi0) ? 0.f : exp2f(S[mt][s][1]);
                    float e2 = (jc     == qi1) ? 0.f : exp2f(S[mt][s][2]);
                    float e3 = (jc + 1 == qi1) ? 0.f : exp2f(S[mt][s][3]);
                    l[mt][0] += e0 + e1;
                    l[mt][1] += e2 + e3;
                    ep[mt][s][0] = pkh(e0, e1);
                    ep[mt][s][1] = pkh(e2, e3);
                }
            }

#pragma unroll
            for (int ks2 = 0; ks2 < 4; ks2++) {
#pragma unroll
                for (int ntp = 0; ntp < 4; ntp++) {
                    uint32_t b0, b1, b2, b3;
                    int rr = 16 * (4 * half + ks2) + (lane & 7) + ((lane >> 3) & 1) * 8;
                    int cc = 2 * ntp + (lane >> 4);
                    ldsm4t(b0, b1, b2, b3, Vs + swz(rr, cc));
#pragma unroll
                    for (int mt = 0; mt < 2; mt++) {
                        uint32_t ap[4] = { ep[mt][2 * ks2][0], ep[mt][2 * ks2][1],
                                           ep[mt][2 * ks2 + 1][0], ep[mt][2 * ks2 + 1][1] };
                        mma_f16(O[mt][2 * ntp],     ap, b0, b1);
                        mma_f16(O[mt][2 * ntp + 1], ap, b2, b3);
                    }
                }
            }
        }
        // no end-of-loop barrier: 4-stage ring guarantees no overwrite hazard
    }

#pragma unroll
    for (int mt = 0; mt < 2; mt++) {
#pragma unroll
        for (int i = 0; i < 2; i++) {
            float li = l[mt][i];
            li += __shfl_xor_sync(0xffffffffu, li, 1);
            li += __shfl_xor_sync(0xffffffffu, li, 2);
            const float inv = 1.f / li;
            const size_t gm = (size_t)(b * 2048 + rbase + 16 * mt + 8 * i);
#pragma unroll
            for (int nt = 0; nt < 8; nt++) {
                const int d = 8 * nt + 2 * (lane & 3);
                size_t idx = gm * INNER + h * DHEAD + d;
                *reinterpret_cast<uint32_t*>(aout + idx) =
                    pkh(O[mt][nt][2 * i] * inv, O[mt][nt][2 * i + 1] * inv);
            }
        }
    }
}

// ---------------- launch -----------------------------------------------------
extern "C" void kernel_launch(void* const* d_in, const int* in_sizes, int n_in,
                              void* d_out, int out_size) {
    const float* x        = (const float*)d_in[0];
    const float* W_qkv    = (const float*)d_in[1];
    const float* log_temp = (const float*)d_in[2];
    const float* W_out    = (const float*)d_in[3];
    const float* b_out    = (const float*)d_in[4];
    float* out = (float*)d_out;

    __half *xh, *wq, *wo, *q, *k, *v, *a;
    cudaGetSymbolAddress((void**)&xh, g_x);
    cudaGetSymbolAddress((void**)&wq, g_wq);
    cudaGetSymbolAddress((void**)&wo, g_wo);
    cudaGetSymbolAddress((void**)&q, g_q);
    cudaGetSymbolAddress((void**)&k, g_k);
    cudaGetSymbolAddress((void**)&v, g_v);
    cudaGetSymbolAddress((void**)&a, g_a);

    const int GSM = 98304;    // 3 stages x 32KB
    const int ASM = 163840;   // 4 KV stages x 32KB + Q 32KB
    cudaFuncSetAttribute(gemm_mma<0>, cudaFuncAttributeMaxDynamicSharedMemorySize, GSM);
    cudaFuncSetAttribute(gemm_mma<1>, cudaFuncAttributeMaxDynamicSharedMemorySize, GSM);
    cudaFuncSetAttribute(attn_mma,    cudaFuncAttributeMaxDynamicSharedMemorySize, ASM);

    k_convert<<<5120, 256>>>(x, W_qkv, W_out, xh, wq, wo);

    // 1) QKV projection (q pre-scaled by exp(log_temp)*log2e)
    gemm_mma<0><<<dim3(12, 64), 256, GSM>>>(xh, wq, DIMX, q, k, v,
                                            log_temp, nullptr, nullptr);
    // 2) attention (q-tile 256, 4-stage ring, 1 barrier/tile)
    attn_mma<<<dim3(SSEQ / 256, BB * HEADS), 256, ASM>>>(q, k, v, a);
    // 3) output projection + bias -> fp32
    gemm_mma<1><<<dim3(4, 64), 256, GSM>>>(a, wo, INNER, nullptr, nullptr, nullptr,
                                           nullptr, b_out, out);
}